// round 17
// baseline (speedup 1.0000x reference)
#include <cuda_runtime.h>
#include <math.h>
#include <stdint.h>

#define B_  2
#define S_  2048
#define D_  1024
#define H_  16
#define HD_ 64
#define M_  (B_ * S_)    // 4096
#define N3_ (3 * D_)     // 3072

// Scratch for Q/K/V in (b*H+h, s, e) layout. All tf32-rounded.
__device__ float g_Q[(size_t)M_ * D_];      // tf32-rounded, pre-scaled by QSCALE
__device__ float g_K[(size_t)M_ * D_];      // tf32-rounded
__device__ float g_V[(size_t)M_ * D_];      // tf32-rounded

// ---------------------------------------------------------------------------
// TF32 helpers
// ---------------------------------------------------------------------------
__device__ __forceinline__ uint32_t f2tf(float x) {
    uint32_t r;
    asm("cvt.rna.tf32.f32 %0, %1;" : "=r"(r) : "f"(x));
    return r;
}
__device__ __forceinline__ float tf32r(float x) {
    uint32_t r;
    asm("cvt.rna.tf32.f32 %0, %1;" : "=r"(r) : "f"(x));
    return __uint_as_float(r);
}
__device__ __forceinline__ float ex2(float x) {
    float r;
    asm("ex2.approx.f32 %0, %1;" : "=f"(r) : "f"(x));
    return r;
}
__device__ __forceinline__ void mma_tf32(float c[4],
    uint32_t a0, uint32_t a1, uint32_t a2, uint32_t a3,
    uint32_t b0, uint32_t b1)
{
    asm volatile(
        "mma.sync.aligned.m16n8k8.row.col.f32.tf32.tf32.f32 "
        "{%0,%1,%2,%3}, {%4,%5,%6,%7}, {%8,%9}, {%0,%1,%2,%3};"
        : "+f"(c[0]), "+f"(c[1]), "+f"(c[2]), "+f"(c[3])
        : "r"(a0), "r"(a1), "r"(a2), "r"(a3), "r"(b0), "r"(b1));
}

// Q scale: 1/sqrt(64) * log2(e) -> scores in log2 domain, softmax via ex2
#define QSCALE 0.1803368801111204f

// ---------------------------------------------------------------------------
// Kernel 1: QKV projection, single-pass TF32 MMA, BK=64 (16 slabs):
// barriers halve again vs BK=32 (the R16 win, reapplied). Same global
// k-order -> bit-identical output. Dynamic smem:
//   Ahi [128][68] (4g+t banks c-free) + Whi [64][136] (8t+g c-free) = 68 KB.
// BM=128, BN=128, BK=64, 256 threads, warps 4(M)x2(N), warp tile 32x64.
// ---------------------------------------------------------------------------
#define GP_A 68
#define GP_W 136
#define SM_A  (128 * GP_A)    // 8704 floats
#define SM_W  (64 * GP_W)     // 8704 floats
#define QKV_SMEM_BYTES ((SM_A + SM_W) * (int)sizeof(float))   // 69632

__global__ __launch_bounds__(256, 2) void qkv_mma_kernel(
    const float* __restrict__ A, const float* __restrict__ W,
    const float* __restrict__ qbias, const float* __restrict__ vbias)
{
    extern __shared__ float qsm[];
    float* Ahi = qsm;             // [128][GP_A]
    float* Whi = qsm + SM_A;      // [64][GP_W]

    const int tid  = threadIdx.x;
    const int warp = tid >> 5;
    const int lane = tid & 31;
    const int g    = lane >> 2;
    const int t    = lane & 3;
    const int bm   = blockIdx.y * 128;
    const int bn   = blockIdx.x * 128;
    const int warpM = (warp >> 1) * 32;
    const int warpN = (warp & 1) * 64;

    float C[2][8][4];
    #pragma unroll
    for (int mf = 0; mf < 2; mf++)
        #pragma unroll
        for (int nf = 0; nf < 8; nf++)
            #pragma unroll
            for (int j = 0; j < 4; j++) C[mf][nf][j] = 0.f;

    const int NS = D_ / 64;   // 16 slabs

    for (int k0 = 0; k0 < NS; k0++) {
        __syncthreads();   // previous MMA phase done reading smem

        // stage: 8 float4 A + 8 float4 W per thread
        #pragma unroll
        for (int i = 0; i < 8; i++) {
            int idx  = tid + i * 256;        // 0..2047
            int ar   = idx >> 4;             // 0..127 (16 float4 per 64-f A row)
            int ac   = (idx & 15) << 2;      // 0..60
            float4 x = *(const float4*)(A + (size_t)(bm + ar) * D_ + k0 * 64 + ac);
            *(float4*)&Ahi[ar * GP_A + ac] =
                make_float4(tf32r(x.x), tf32r(x.y), tf32r(x.z), tf32r(x.w));

            int wr   = idx >> 5;             // 0..63 (32 float4 per 128-f W row)
            int wc   = (idx & 31) << 2;      // 0..124
            float4 y = *(const float4*)(W + (size_t)(k0 * 64 + wr) * N3_ + bn + wc);
            *(float4*)&Whi[wr * GP_W + wc] =
                make_float4(tf32r(y.x), tf32r(y.y), tf32r(y.z), tf32r(y.w));
        }
        __syncthreads();

        #pragma unroll
        for (int kc = 0; kc < 8; kc++) {
            uint32_t ah[2][4];
            #pragma unroll
            for (int mf = 0; mf < 2; mf++) {
                int r0 = (warpM + mf * 16 + g) * GP_A + kc * 8 + t;
                ah[mf][0] = __float_as_uint(Ahi[r0]);
                ah[mf][1] = __float_as_uint(Ahi[r0 + 8 * GP_A]);
                ah[mf][2] = __float_as_uint(Ahi[r0 + 4]);
                ah[mf][3] = __float_as_uint(Ahi[r0 + 8 * GP_A + 4]);
            }
            #pragma unroll
            for (int nf = 0; nf < 8; nf++) {
                int n  = warpN + nf * 8 + g;
                int kb = (kc * 8 + t) * GP_W + n;
                uint32_t bh0 = __float_as_uint(Whi[kb]);
                uint32_t bh1 = __float_as_uint(Whi[kb + 4 * GP_W]);
                #pragma unroll
                for (int mf = 0; mf < 2; mf++)
                    mma_tf32(C[mf][nf], ah[mf][0], ah[mf][1], ah[mf][2], ah[mf][3], bh0, bh1);
            }
        }
    }

    // Epilogue: scatter into (b*H+h, s, e); all three tf32-rounded.
    const int which = bn >> 10;
    #pragma unroll
    for (int mf = 0; mf < 2; mf++) {
        int mrow = bm + warpM + mf * 16 + g;
        int b = mrow >> 11;
        int s = mrow & (S_ - 1);
        #pragma unroll
        for (int nf = 0; nf < 8; nf++) {
            int ncol = bn + warpN + nf * 8 + 2 * t;
            int d = ncol & (D_ - 1);
            int h = d >> 6;
            int e = d & 63;
            size_t i0 = ((size_t)(b * H_ + h) * S_ + s) * HD_ + e;
            size_t i1 = i0 + 8 * HD_;
            float c0 = C[mf][nf][0], c1 = C[mf][nf][1];
            float c2 = C[mf][nf][2], c3 = C[mf][nf][3];
            if (which == 0) {
                float b0 = qbias[d], b1 = qbias[d + 1];
                *(float2*)&g_Q[i0] = make_float2(tf32r((c0 + b0) * QSCALE),
                                                 tf32r((c1 + b1) * QSCALE));
                *(float2*)&g_Q[i1] = make_float2(tf32r((c2 + b0) * QSCALE),
                                                 tf32r((c3 + b1) * QSCALE));
            } else if (which == 1) {
                *(float2*)&g_K[i0] = make_float2(tf32r(c0), tf32r(c1));
                *(float2*)&g_K[i1] = make_float2(tf32r(c2), tf32r(c3));
            } else {
                float b0 = vbias[d], b1 = vbias[d + 1];
                *(float2*)&g_V[i0] = make_float2(tf32r(c0 + b0), tf32r(c1 + b1));
                *(float2*)&g_V[i1] = make_float2(tf32r(c2 + b0), tf32r(c3 + b1));
            }
        }
    }
}

// ---------------------------------------------------------------------------
// Kernel 2: flash attention — R12 champion compute structure, with K/V
// staged 128 keys per barrier pair (two 64-key sub-chunks computed per
// stage, in the original order -> math sequence identical to attn7).
// Block = 128 threads (4 warps), warp tile M=32, Br=128.
// smem: Qs [128][68] + Khi [128][68] + Vt [128][72] = 106496 B -> 2 blk/SM.
// ---------------------------------------------------------------------------
#define QP 68
#define KP 68
#define VP 72
#define SM_Q  (128 * QP)
#define SM_KB (128 * KP)
#define SM_VB (128 * VP)
#define ATTN_SMEM_BYTES ((SM_Q + SM_KB + SM_VB) * (int)sizeof(float)) // 106496

__global__ __launch_bounds__(128, 2) void attn11_kernel(float* __restrict__ out)
{
    extern __shared__ float sm[];
    float* Qs  = sm;              // [128][QP] tf32-rounded, pre-scaled
    float* Kb  = Qs + SM_Q;       // [128][KP] tf32-rounded
    float* Vb  = Kb + SM_KB;      // [128][VP] tf32-rounded

    const int tid  = threadIdx.x;
    const int warp = tid >> 5;
    const int lane = tid & 31;
    const int g    = lane >> 2;
    const int t    = lane & 3;
    const int wm   = warp * 32;
    const int bh   = blockIdx.y;
    const int qt   = blockIdx.x;

    const float* Qg = g_Q + ((size_t)bh * S_ + qt * 128) * HD_;
    const float* Kg = g_K + (size_t)bh * S_ * HD_;
    const float* Vg = g_V + (size_t)bh * S_ * HD_;

    #pragma unroll
    for (int i = 0; i < 16; i++) {
        int idx = tid + i * 128;
        int row = idx >> 4;
        int col = (idx & 15) << 2;
        *(float4*)&Qs[row * QP + col] = *(const float4*)(Qg + row * HD_ + col);
    }

    float m[2][2], l[2][2];
    #pragma unroll
    for (int mf = 0; mf < 2; mf++) {
        m[mf][0] = -INFINITY; m[mf][1] = -INFINITY;
        l[mf][0] = 0.f;       l[mf][1] = 0.f;
    }
    float O[2][8][4];
    #pragma unroll
    for (int mf = 0; mf < 2; mf++)
        #pragma unroll
        for (int nt = 0; nt < 8; nt++)
            #pragma unroll
            for (int j = 0; j < 4; j++) O[mf][nt][j] = 0.f;

    for (int kt = 0; kt < S_ / 128; kt++) {
        __syncthreads();

        // ---- stage 128 keys of K and V (16 float4 each per thread) ----
        const float* Kt = Kg + (size_t)kt * 128 * HD_;
        const float* Vp = Vg + (size_t)kt * 128 * HD_;
        #pragma unroll
        for (int i = 0; i < 16; i++) {
            int idx = tid + i * 128;
            int row = idx >> 4;
            int col = (idx & 15) << 2;
            *(float4*)&Kb[row * KP + col] = *(const float4*)(Kt + row * HD_ + col);
            *(float4*)&Vb[row * VP + col] = *(const float4*)(Vp + row * HD_ + col);
        }
        __syncthreads();

        // ---- two 64-key sub-chunks, original key order ----
        #pragma unroll
        for (int sub = 0; sub < 2; sub++) {
            const float* Khi = Kb + sub * 64 * KP;
            const float* Vt  = Vb + sub * 64 * VP;

            // ---- scores (log2 domain): 1 MMA ----
            float Sf[2][8][4];
            #pragma unroll
            for (int mf = 0; mf < 2; mf++)
                #pragma unroll
                for (int nt = 0; nt < 8; nt++)
                    #pragma unroll
                    for (int j = 0; j < 4; j++) Sf[mf][nt][j] = 0.f;

            #pragma unroll
            for (int kc = 0; kc < 8; kc++) {
                uint32_t ah[2][4];
                #pragma unroll
                for (int mf = 0; mf < 2; mf++) {
                    int qi = (wm + mf * 16 + g) * QP + kc * 8 + t;
                    ah[mf][0] = __float_as_uint(Qs[qi]);
                    ah[mf][1] = __float_as_uint(Qs[qi + 8 * QP]);
                    ah[mf][2] = __float_as_uint(Qs[qi + 4]);
                    ah[mf][3] = __float_as_uint(Qs[qi + 8 * QP + 4]);
                }
                #pragma unroll
                for (int nt = 0; nt < 8; nt++) {
                    int kb = (nt * 8 + g) * KP + kc * 8 + t;
                    uint32_t bh0 = __float_as_uint(Khi[kb]);
                    uint32_t bh1 = __float_as_uint(Khi[kb + 4]);
                    #pragma unroll
                    for (int mf = 0; mf < 2; mf++)
                        mma_tf32(Sf[mf][nt], ah[mf][0], ah[mf][1], ah[mf][2], ah[mf][3], bh0, bh1);
                }
            }

            // ---- online softmax (base-2) ----
            #pragma unroll
            for (int mf = 0; mf < 2; mf++) {
                float mx0 = -INFINITY, mx1 = -INFINITY;
                #pragma unroll
                for (int nt = 0; nt < 8; nt++) {
                    mx0 = fmaxf(mx0, fmaxf(Sf[mf][nt][0], Sf[mf][nt][1]));
                    mx1 = fmaxf(mx1, fmaxf(Sf[mf][nt][2], Sf[mf][nt][3]));
                }
                mx0 = fmaxf(mx0, __shfl_xor_sync(0xffffffffu, mx0, 1));
                mx0 = fmaxf(mx0, __shfl_xor_sync(0xffffffffu, mx0, 2));
                mx1 = fmaxf(mx1, __shfl_xor_sync(0xffffffffu, mx1, 1));
                mx1 = fmaxf(mx1, __shfl_xor_sync(0xffffffffu, mx1, 2));

                float mn0 = fmaxf(m[mf][0], mx0);
                float mn1 = fmaxf(m[mf][1], mx1);
                float alp0 = ex2(m[mf][0] - mn0);
                float alp1 = ex2(m[mf][1] - mn1);

                float ls0 = 0.f, ls1 = 0.f;
                #pragma unroll
                for (int nt = 0; nt < 8; nt++) {
                    Sf[mf][nt][0] = ex2(Sf[mf][nt][0] - mn0);
                    Sf[mf][nt][1] = ex2(Sf[mf][nt][1] - mn0);
                    Sf[mf][nt][2] = ex2(Sf[mf][nt][2] - mn1);
                    Sf[mf][nt][3] = ex2(Sf[mf][nt][3] - mn1);
                    ls0 += Sf[mf][nt][0] + Sf[mf][nt][1];
                    ls1 += Sf[mf][nt][2] + Sf[mf][nt][3];
                }
                ls0 += __shfl_xor_sync(0xffffffffu, ls0, 1);
                ls0 += __shfl_xor_sync(0xffffffffu, ls0, 2);
                ls1 += __shfl_xor_sync(0xffffffffu, ls1, 1);
                ls1 += __shfl_xor_sync(0xffffffffu, ls1, 2);

                l[mf][0] = l[mf][0] * alp0 + ls0;  m[mf][0] = mn0;
                l[mf][1] = l[mf][1] * alp1 + ls1;  m[mf][1] = mn1;

                #pragma unroll
                for (int nt = 0; nt < 8; nt++) {
                    O[mf][nt][0] *= alp0;  O[mf][nt][1] *= alp0;
                    O[mf][nt][2] *= alp1;  O[mf][nt][3] *= alp1;
                }
            }

            // ---- O += P @ V ----
            const int src0 = (lane & ~3) + (t >> 1);
            const int src2 = src0 + 2;
            const bool odd = (t & 1);

            #pragma unroll
            for (int kc = 0; kc < 8; kc++) {
                uint32_t a[2][4];
                #pragma unroll
                for (int mf = 0; mf < 2; mf++) {
                    float e0 = __shfl_sync(0xffffffffu, Sf[mf][kc][0], src0);
                    float e1 = __shfl_sync(0xffffffffu, Sf[mf][kc][1], src0);
                    float f0 = __shfl_sync(0xffffffffu, Sf[mf][kc][0], src2);
                    float f1 = __shfl_sync(0xffffffffu, Sf[mf][kc][1], src2);
                    float h0 = __shfl_sync(0xffffffffu, Sf[mf][kc][2], src0);
                    float h1 = __shfl_sync(0xffffffffu, Sf[mf][kc][3], src0);
                    float i0 = __shfl_sync(0xffffffffu, Sf[mf][kc][2], src2);
                    float i1 = __shfl_sync(0xffffffffu, Sf[mf][kc][3], src2);
                    a[mf][0] = f2tf(odd ? e1 : e0);
                    a[mf][1] = f2tf(odd ? h1 : h0);
                    a[mf][2] = f2tf(odd ? f1 : f0);
                    a[mf][3] = f2tf(odd ? i1 : i0);
                }
                #pragma unroll
                for (int nt = 0; nt < 8; nt++) {
                    int vi = (kc * 8 + t) * VP + nt * 8 + g;
                    uint32_t bh0 = __float_as_uint(Vt[vi]);
                    uint32_t bh1 = __float_as_uint(Vt[vi + 4 * VP]);
                    #pragma unroll
                    for (int mf = 0; mf < 2; mf++)
                        mma_tf32(O[mf][nt], a[mf][0], a[mf][1], a[mf][2], a[mf][3], bh0, bh1);
                }
            }
        }
    }

    // ---- epilogue ----
    int b = bh >> 4;
    int h = bh & 15;
    #pragma unroll
    for (int mf = 0; mf < 2; mf++) {
        float inv0 = 1.f / l[mf][0];
        float inv1 = 1.f / l[mf][1];
        int srow = qt * 128 + wm + mf * 16 + g;
        size_t base0 = ((size_t)(b * S_ + srow) * H_ + h) * HD_;
        size_t base1 = base0 + (size_t)8 * H_ * HD_;
        #pragma unroll
        for (int nt = 0; nt < 8; nt++) {
            int col = nt * 8 + 2 * t;
            *(float2*)&out[base0 + col] =
                make_float2(O[mf][nt][0] * inv0, O[mf][nt][1] * inv0);
            *(float2*)&out[base1 + col] =
                make_float2(O[mf][nt][2] * inv1, O[mf][nt][3] * inv1);
        }
    }
}

extern "C" void kernel_launch(void* const* d_in, const int* in_sizes, int n_in,
                              void* d_out, int out_size)
{
    const float* hs = (const float*)d_in[0];
    const float* w  = (const float*)d_in[1];
    const float* qb = (const float*)d_in[2];
    const float* vb = (const float*)d_in[3];
    float* out = (float*)d_out;

    cudaFuncSetAttribute(qkv_mma_kernel,
                         cudaFuncAttributeMaxDynamicSharedMemorySize, QKV_SMEM_BYTES);
    dim3 g1(N3_ / 128, M_ / 128);   // 24 x 32
    qkv_mma_kernel<<<g1, 256, QKV_SMEM_BYTES>>>(hs, w, qb, vb);

    cudaFuncSetAttribute(attn11_kernel,
                         cudaFuncAttributeMaxDynamicSharedMemorySize, ATTN_SMEM_BYTES);
    dim3 g2(S_ / 128, B_ * H_);     // 16 x 32
    attn11_kernel<<<g2, 128, ATTN_SMEM_BYTES>>>(out);
}